// round 3
// baseline (speedup 1.0000x reference)
#include <cuda_runtime.h>

typedef unsigned long long ull;
typedef long long ll;

#define S_LEN   1024
#define D_DIM   64
#define NPOS    64
#define CH      32                  // keys per chunk = lanes
#define NCH     (S_LEN / CH)
#define WARPS   4
#define RPW     16                  // rows per warp
#define CTA_ROWS (WARPS * RPW)      // 64
#define SCALE_F 0.125f

#define PE_STRIDE 68
#define LG_STRIDE 66
#define SMEM_FLOATS (NPOS * PE_STRIDE + CTA_ROWS * LG_STRIDE)
#define SMEM_BYTES  (SMEM_FLOATS * 4)   // ~34.3 KB

#define FULLM 0xffffffffu

__device__ __forceinline__ ull fma2(ull a, ull b, ull c) {
    ull d;
    asm("fma.rn.f32x2 %0, %1, %2, %3;" : "=l"(d) : "l"(a), "l"(b), "l"(c));
    return d;
}
__device__ __forceinline__ float hsum2(ull a) {
    unsigned lo, hi;
    asm("mov.b64 {%0, %1}, %2;" : "=r"(lo), "=r"(hi) : "l"(a));
    return __uint_as_float(lo) + __uint_as_float(hi);
}
__device__ __forceinline__ float sigm(float x) {
    return __fdividef(1.0f, 1.0f + __expf(-x));
}

__global__ void __launch_bounds__(WARPS * 32, 4)
cope_kernel(const float* __restrict__ q, const float* __restrict__ kmat,
            const float* __restrict__ pos_emb, const int* __restrict__ flag_p,
            float* __restrict__ out)
{
    extern __shared__ float smem[];
    float* pe_t = smem;                         // [NPOS][68] transposed pos_emb
    float* lgt  = smem + NPOS * PE_STRIDE;      // [CTA_ROWS][66] logits_int per row

    const int tid  = threadIdx.x;
    const int wid  = tid >> 5;
    const int lane = tid & 31;

    // ---- Phase 0: pos_emb -> smem transposed: pe_t[n][d] = pos_emb[d*NPOS + n]
    for (int i = tid; i < D_DIM * NPOS; i += WARPS * 32) {
        int d = i >> 6, n = i & 63;
        pe_t[n * PE_STRIDE + d] = pos_emb[i];
    }
    __syncthreads();

    // ---- Phase 1: logits_int[row][n] = base[row]·pos_emb[:,n]; 2 threads per row
    {
        const int lrow  = tid >> 1;
        const int nbase = (tid & 1) * 32;
        const ll  grow  = (ll)blockIdx.x * CTA_ROWS + lrow;
        const int flag  = *flag_p;
        const ulonglong2* bp =
            (const ulonglong2*)((flag ? q : kmat) + grow * D_DIM);
        ull qp[32];
        #pragma unroll
        for (int j = 0; j < 16; ++j) { ulonglong2 v = bp[j]; qp[2*j] = v.x; qp[2*j+1] = v.y; }
        for (int n = nbase; n < nbase + 32; ++n) {
            const ulonglong2* pr = (const ulonglong2*)(pe_t + n * PE_STRIDE);
            ull acc = 0ull;
            #pragma unroll
            for (int j = 0; j < 16; ++j) {
                ulonglong2 v = pr[j];
                acc = fma2(qp[2*j],     v.x, acc);
                acc = fma2(qp[2*j + 1], v.y, acc);
            }
            lgt[lrow * LG_STRIDE + n] = hsum2(acc);
        }
        if (tid & 1) lgt[lrow * LG_STRIDE + 64] = 0.0f;  // guard for ceil gather at pos==63
    }
    __syncwarp();   // lgt rows for warp w are written by warp w's own threads

    // ---- Phase 2: lane = key; reverse chunk sweep with per-row saturation exit
    const int b        = blockIdx.x >> 4;                    // 16 CTAs per batch (1024/64)
    const int lrow0    = wid * RPW;
    const ll  growbase = (ll)blockIdx.x * CTA_ROWS + lrow0;

    float    carry  = (lane < RPW) ? 0.0f : 1e9f;            // lane r holds row r's carry
    unsigned filled = 0xFFFF0000u;

    for (int t = NCH - 1; t >= 0; --t) {
        unsigned sat   = __ballot_sync(FULLM, carry >= 63.0f);
        unsigned newly = sat & ~filled;
        filled |= sat;
        // newly-saturated rows: bulk fill all remaining keys with logits[63]
        while (newly) {
            int r = __ffs(newly) - 1; newly &= newly - 1;
            float  val = lgt[(lrow0 + r) * LG_STRIDE + 63];  // uniform LDS broadcast
            float4 vv  = make_float4(val, val, val, val);
            float* dst = out + (growbase + r) * S_LEN;
            const int cnt = (t + 1) * CH;
            for (int c = 4 * lane; c < cnt; c += 128) *(float4*)(dst + c) = vv;
        }
        if (filled == FULLM) break;

        const int kb = t * CH;
        // load this lane's key vector into registers (reused across 16 rows)
        ull kv[32];
        {
            const ulonglong2* kp =
                (const ulonglong2*)(kmat + ((ll)b * S_LEN + kb + lane) * D_DIM);
            #pragma unroll
            for (int j = 0; j < 16; ++j) { ulonglong2 v = kp[j]; kv[2*j] = v.x; kv[2*j+1] = v.y; }
        }

        for (int r0 = 0; r0 < RPW; r0 += 4) {
            if (((sat >> r0) & 0xFu) == 0xFu) continue;      // quad fully saturated
            float c0 = __shfl_sync(FULLM, carry, r0);
            float c1 = __shfl_sync(FULLM, carry, r0 + 1);
            float c2 = __shfl_sync(FULLM, carry, r0 + 2);
            float c3 = __shfl_sync(FULLM, carry, r0 + 3);

            const ulonglong2* q0 =
                (const ulonglong2*)(q + (growbase + r0) * D_DIM);  // 4 rows contiguous
            ull a0 = 0, a1 = 0, a2 = 0, a3 = 0;
            #pragma unroll
            for (int i = 0; i < 16; ++i) {
                ulonglong2 v0 = q0[i], v1 = q0[16 + i], v2 = q0[32 + i], v3 = q0[48 + i];
                a0 = fma2(v0.x, kv[2*i], a0); a0 = fma2(v0.y, kv[2*i + 1], a0);
                a1 = fma2(v1.x, kv[2*i], a1); a1 = fma2(v1.y, kv[2*i + 1], a1);
                a2 = fma2(v2.x, kv[2*i], a2); a2 = fma2(v2.y, kv[2*i + 1], a2);
                a3 = fma2(v3.x, kv[2*i], a3); a3 = fma2(v3.y, kv[2*i + 1], a3);
            }
            float s0 = sigm(hsum2(a0) * SCALE_F);
            float s1 = sigm(hsum2(a1) * SCALE_F);
            float s2 = sigm(hsum2(a2) * SCALE_F);
            float s3 = sigm(hsum2(a3) * SCALE_F);

            // warp reverse-inclusive (suffix) scan: s_l = sum_{j>=l} g_j
            #pragma unroll
            for (int off = 1; off < 32; off <<= 1) {
                float u0 = __shfl_down_sync(FULLM, s0, off);
                float u1 = __shfl_down_sync(FULLM, s1, off);
                float u2 = __shfl_down_sync(FULLM, s2, off);
                float u3 = __shfl_down_sync(FULLM, s3, off);
                if (lane + off < 32) { s0 += u0; s1 += u1; s2 += u2; s3 += u3; }
            }
            float t0 = __shfl_sync(FULLM, s0, 0);
            float t1 = __shfl_sync(FULLM, s1, 0);
            float t2 = __shfl_sync(FULLM, s2, 0);
            float t3 = __shfl_sync(FULLM, s3, 0);

            #define EMIT(J, CJ, SJ)                                                  \
            {                                                                        \
                float pos = fminf((CJ) + (SJ), 63.0f);                               \
                float pf  = floorf(pos);                                             \
                int   ip  = (int)pf;                                                 \
                float w   = pos - pf;                                                \
                const float* lr = lgt + (lrow0 + r0 + (J)) * LG_STRIDE;              \
                float lf = lr[ip], lc = lr[ip + 1];                                  \
                out[(growbase + r0 + (J)) * S_LEN + kb + lane] =                     \
                    lc * w + lf * (1.0f - w);                                        \
            }
            EMIT(0, c0, s0) EMIT(1, c1, s1) EMIT(2, c2, s2) EMIT(3, c3, s3)
            #undef EMIT

            if      (lane == r0)     carry = c0 + t0;
            else if (lane == r0 + 1) carry = c1 + t1;
            else if (lane == r0 + 2) carry = c2 + t2;
            else if (lane == r0 + 3) carry = c3 + t3;
        }
    }
}

extern "C" void kernel_launch(void* const* d_in, const int* in_sizes, int n_in,
                              void* d_out, int out_size) {
    const float* q    = (const float*)d_in[0];
    const float* k    = (const float*)d_in[1];
    // d_in[2] = v (unused in mode 0)
    const float* pe   = (const float*)d_in[3];
    // d_in[4] = w_k (unused)
    const int*   flag = (const int*)d_in[5];
    float* out = (float*)d_out;

    cudaFuncSetAttribute(cope_kernel, cudaFuncAttributeMaxDynamicSharedMemorySize, SMEM_BYTES);
    const int grid = (32 * S_LEN) / CTA_ROWS;   // 512 CTAs
    cope_kernel<<<grid, WARPS * 32, SMEM_BYTES>>>(q, k, pe, flag, out);
}